// round 17
// baseline (speedup 1.0000x reference)
#include <cuda_runtime.h>
#include <math.h>
#include <stdint.h>

#define BB 8
#define HH 1024
#define DD 4
#define NTB 32                    // 32x32 tiles per dim
#define NPAIR (NTB*(NTB+1)/2)     // 528 tile-pairs

// Partial sums: [b][i][jt][8] fp32 (s1 d0..3, s2 d0..3). Each slot written
// exactly once by exactly one block -> no init, deterministic.
__device__ __align__(16) float g_part[(size_t)BB * HH * NTB * 8];

typedef unsigned long long u64;

__device__ __forceinline__ u64 pack2(float x, float y) {
    u64 r; asm("mov.b64 %0, {%1, %2};" : "=l"(r) : "f"(x), "f"(y)); return r;
}
__device__ __forceinline__ u64 ffma2(u64 a, u64 b, u64 c) {
    u64 d; asm("fma.rn.f32x2 %0, %1, %2, %3;" : "=l"(d) : "l"(a), "l"(b), "l"(c)); return d;
}
__device__ __forceinline__ float2 unpk2(u64 v) {
    float x, y; asm("mov.b64 {%0, %1}, %2;" : "=f"(x), "=f"(y) : "l"(v));
    return make_float2(x, y);
}

// ---------------------------------------------------------------------------
// Fused kernel: symmetrize+relu+rotate+reduce in one pass over A.
// Block = tile-pair (ti<=tj), 256 threads: r = tid>>3 (row 0..31), cc = tid&7
// (j-chunk). Alpha trig in regs (8 sincos/thread). Theta trig in SMEM,
// k-major conflict-free layout, staged per 4-batch half (8 sincos/thread).
// Per batch: both directions' 8 partial sums per row, 8-lane shuffle reduce,
// write g_part.
// ---------------------------------------------------------------------------
__global__ __launch_bounds__(256)
void vk_fused_kernel(const float* __restrict__ A,
                     const float* __restrict__ alpha,
                     const float* __restrict__ theta) {
    __shared__ float tA[32][33], tB[32][33];  // stride 33: conflict-free transpose
    // theta trig, 4 batches: flat = t*512 + bq*128 + k*32 + cc*4 + d
    __shared__ float sS[1024], sC[1024];

    // triangular decode of blockIdx.x -> (ti, tj)
    int p = blockIdx.x;
    int ti = 0;
    while (p >= NTB - ti) { p -= NTB - ti; ti++; }
    const int tj = ti + p;
    const int i0 = ti * 32, j0 = tj * 32;
    const bool diag = (ti == tj);

    const int tid = threadIdx.x;
    const int r  = tid >> 3;
    const int cc = tid & 7;
    const int c  = cc * 4;

    // batch-invariant alpha trig (0.5 of symmetrization folded in)
    float2 csij[4], csji[4];
    {
        float4 a4 = *(const float4*)(alpha + (size_t)(i0 + r) * HH + j0 + c);
        float av[4] = {a4.x, a4.y, a4.z, a4.w};
        #pragma unroll
        for (int k = 0; k < 4; k++) {
            float s, co; sincosf(av[k], &s, &co);
            csij[k] = make_float2(0.5f * co, 0.5f * s);
        }
    }
    {
        float4 a4 = *(const float4*)(alpha + (size_t)(j0 + r) * HH + i0 + c);
        float av[4] = {a4.x, a4.y, a4.z, a4.w};
        #pragma unroll
        for (int k = 0; k < 4; k++) {
            float s, co; sincosf(av[k], &s, &co);
            csji[k] = make_float2(0.5f * co, 0.5f * s);
        }
    }

    for (int h = 0; h < 2; h++) {
        __syncthreads();   // previous half's computes done reading sS/sC
        // stage theta trig for batches h*4 .. h*4+3 (1024 values, 4/thread)
        #pragma unroll
        for (int q = 0; q < 4; q++) {
            int flat = q * 256 + tid;
            int d   = flat & 3;
            int ccs = (flat >> 2) & 7;
            int k   = (flat >> 5) & 3;
            int bq  = (flat >> 7) & 3;
            int t   = (flat >> 9) & 1;
            int j   = (t ? j0 : i0) + ccs * 4 + k;
            int b   = h * 4 + bq;
            float s, co;
            sincosf(theta[((size_t)b * HH + j) * DD + d], &s, &co);
            sS[flat] = s; sC[flat] = co;
        }

        for (int bq = 0; bq < 4; bq++) {
            const int b = h * 4 + bq;
            const float* Ab = A + (size_t)b * HH * HH;
            float4 va = *(const float4*)(Ab + (size_t)(i0 + r) * HH + j0 + c);
            float4 vb = *(const float4*)(Ab + (size_t)(j0 + r) * HH + i0 + c);
            __syncthreads();   // prior batch's tile reads done; trig visible (bq=0)
            tA[r][c + 0] = va.x; tA[r][c + 1] = va.y;
            tA[r][c + 2] = va.z; tA[r][c + 3] = va.w;
            tB[r][c + 0] = vb.x; tB[r][c + 1] = vb.y;
            tB[r][c + 2] = vb.z; tB[r][c + 3] = vb.w;
            __syncthreads();

            u64 acc[8] = {0, 0, 0, 0, 0, 0, 0, 0};
            #pragma unroll
            for (int k = 0; k < 4; k++) {
                const int tb = bq * 128 + k * 32 + cc * 4;
                // dir ij: rows of ti, j in tj (tile index t=1)
                ulonglong2 Sj = *(const ulonglong2*)&sS[512 + tb];
                ulonglong2 Cj = *(const ulonglong2*)&sC[512 + tb];
                float a1 = fmaxf(tA[r][c + k] + tB[c + k][r], 0.f);
                float w1 = a1 * csij[k].x, w2 = a1 * csij[k].y;
                u64 w1p = pack2(w1, w1), w2p = pack2(w2, w2), n2p = pack2(-w2, -w2);
                acc[0] = ffma2(w1p, Sj.x, acc[0]); acc[0] = ffma2(n2p, Cj.x, acc[0]);
                acc[1] = ffma2(w1p, Sj.y, acc[1]); acc[1] = ffma2(n2p, Cj.y, acc[1]);
                acc[2] = ffma2(w1p, Cj.x, acc[2]); acc[2] = ffma2(w2p, Sj.x, acc[2]);
                acc[3] = ffma2(w1p, Cj.y, acc[3]); acc[3] = ffma2(w2p, Sj.y, acc[3]);
                if (!diag) {
                    // dir ji: rows of tj, j in ti (tile index t=0)
                    ulonglong2 Si = *(const ulonglong2*)&sS[tb];
                    ulonglong2 Ci = *(const ulonglong2*)&sC[tb];
                    float a2 = fmaxf(tB[r][c + k] + tA[c + k][r], 0.f);
                    float u1 = a2 * csji[k].x, u2 = a2 * csji[k].y;
                    u64 u1p = pack2(u1, u1), u2p = pack2(u2, u2), m2p = pack2(-u2, -u2);
                    acc[4] = ffma2(u1p, Si.x, acc[4]); acc[4] = ffma2(m2p, Ci.x, acc[4]);
                    acc[5] = ffma2(u1p, Si.y, acc[5]); acc[5] = ffma2(m2p, Ci.y, acc[5]);
                    acc[6] = ffma2(u1p, Ci.x, acc[6]); acc[6] = ffma2(u2p, Si.x, acc[6]);
                    acc[7] = ffma2(u1p, Ci.y, acc[7]); acc[7] = ffma2(u2p, Si.y, acc[7]);
                }
            }

            // unpack -> v[16]; reduce over the 8 lanes sharing a row
            float v[16];
            #pragma unroll
            for (int q = 0; q < 8; q++) {
                float2 t2 = unpk2(acc[q]);
                v[q * 2] = t2.x; v[q * 2 + 1] = t2.y;
            }
            // v order per dir: [s1d0,s1d1,s1d2,s1d3,s2d0,s2d1,s2d2,s2d3]
            if (!diag) {
                #pragma unroll
                for (int off = 1; off < 8; off <<= 1)
                    #pragma unroll
                    for (int q = 0; q < 16; q++)
                        v[q] += __shfl_xor_sync(0xFFFFFFFFu, v[q], off);
            } else {
                #pragma unroll
                for (int off = 1; off < 8; off <<= 1)
                    #pragma unroll
                    for (int q = 0; q < 8; q++)
                        v[q] += __shfl_xor_sync(0xFFFFFFFFu, v[q], off);
            }

            if (cc == 0) {
                size_t o1 = (((size_t)b * HH + i0 + r) * NTB + tj) * 8;
                *(float4*)&g_part[o1]     = make_float4(v[0], v[1], v[2], v[3]);
                *(float4*)&g_part[o1 + 4] = make_float4(v[4], v[5], v[6], v[7]);
                if (!diag) {
                    size_t o2 = (((size_t)b * HH + j0 + r) * NTB + ti) * 8;
                    *(float4*)&g_part[o2]     = make_float4(v[8],  v[9],  v[10], v[11]);
                    *(float4*)&g_part[o2 + 4] = make_float4(v[12], v[13], v[14], v[15]);
                }
            }
        }
    }
}

// ---------------------------------------------------------------------------
// Epilogue: per (b,i) thread sums 32 partials (1KB contiguous), computes its
// own (si,ci) sincos, applies the update formula. 8192 threads total.
// ---------------------------------------------------------------------------
__global__ __launch_bounds__(128)
void vk_epilogue_kernel(const float* __restrict__ theta,
                        const float* __restrict__ gamma,
                        const float* __restrict__ omega,
                        const float* __restrict__ kappa,
                        float* __restrict__ out) {
    const int idx = blockIdx.x * 128 + threadIdx.x;   // 0..8191
    const int b = idx >> 10;
    const int i = idx & 1023;

    const float4* pp = (const float4*)(g_part + ((size_t)b * HH + i) * NTB * 8);
    float4 p0 = make_float4(0.f, 0.f, 0.f, 0.f);   // s1 d0..3
    float4 p1 = make_float4(0.f, 0.f, 0.f, 0.f);   // s2 d0..3
    #pragma unroll 8
    for (int jt = 0; jt < NTB; jt++) {
        float4 q0 = pp[2 * jt];
        float4 q1 = pp[2 * jt + 1];
        p0.x += q0.x; p0.y += q0.y; p0.z += q0.z; p0.w += q0.w;
        p1.x += q1.x; p1.y += q1.y; p1.z += q1.z; p1.w += q1.w;
    }

    const float invH = 1.0f / (float)HH;   // K_COUP=1, DT=1, 0.5 folded upstream
    const size_t base = ((size_t)b * HH + i) * DD;
    float4 tp4 = *(const float4*)(theta + base);
    float4 om4 = *(const float4*)(omega + (size_t)i * DD);
    float4 kp4 = *(const float4*)(kappa + (size_t)i * DD);
    float g = gamma[(size_t)b * HH + i];

    float si0, ci0, si1, ci1, si2, ci2, si3, ci3;
    sincosf(tp4.x, &si0, &ci0);
    sincosf(tp4.y, &si1, &ci1);
    sincosf(tp4.z, &si2, &ci2);
    sincosf(tp4.w, &si3, &ci3);

    float4 rr;
    rr.x = tp4.x + om4.x + invH * (ci0 * p0.x - si0 * p1.x) + kp4.x * (g - tp4.x);
    rr.y = tp4.y + om4.y + invH * (ci1 * p0.y - si1 * p1.y) + kp4.y * (g - tp4.y);
    rr.z = tp4.z + om4.z + invH * (ci2 * p0.z - si2 * p1.z) + kp4.z * (g - tp4.z);
    rr.w = tp4.w + om4.w + invH * (ci3 * p0.w - si3 * p1.w) + kp4.w * (g - tp4.w);
    *(float4*)(out + base) = rr;
}

extern "C" void kernel_launch(void* const* d_in, const int* in_sizes, int n_in,
                              void* d_out, int out_size) {
    const float* theta = (const float*)d_in[0];  // [B,H,D]
    const float* gamma = (const float*)d_in[1];  // [B,H]
    const float* A     = (const float*)d_in[2];  // [B,H,H]
    const float* omega = (const float*)d_in[3];  // [H,D]
    const float* kappa = (const float*)d_in[4];  // [H,D]
    const float* alpha = (const float*)d_in[5];  // [H,H]
    float* out = (float*)d_out;

    vk_fused_kernel<<<NPAIR, 256>>>(A, alpha, theta);
    vk_epilogue_kernel<<<(BB * HH) / 128, 128>>>(theta, gamma, omega, kappa, out);
}